// round 1
// baseline (speedup 1.0000x reference)
#include <cuda_runtime.h>
#include <math.h>

#define MAXN 100000
#define MAXE 3200000

// ---------------- scratch (static device globals; no allocation) -------------
__device__ float g_bufA[(size_t)MAXN * 128]; // hs (scaled XW1), then h1
__device__ float g_bufB[(size_t)MAXN * 128]; // agg1
__device__ float g_h2s [(size_t)MAXN * 64];  // scaled h1@W2
__device__ float g_agg2[(size_t)MAXN * 64];  // agg2
__device__ float g_h2  [(size_t)MAXN * 64];  // post conv2
__device__ float g_a1  [(size_t)MAXN * 64];  // tanh(h2@Wf1+bf1)
__device__ float g_s   [(size_t)MAXN * 8];   // attention logits
__device__ float g_dinv[MAXN];               // deg -> deg^{-1/2}
__device__ float g_Z[8];                     // sum exp(s) per column
__device__ float g_G[512];                   // unnormalized att.T @ h2  [8,64]
__device__ float g_C[64];                    // unnormalized att.T @ att [8,8]

// ---------------- small kernels ----------------------------------------------
__global__ void k_init(int n) {
    int i = blockIdx.x * blockDim.x + threadIdx.x;
    if (i < n)   g_dinv[i] = 1.0f;  // self-loop contributes 1 to degree
    if (i < 512) g_G[i] = 0.0f;
    if (i < 64)  g_C[i] = 0.0f;
    if (i < 8)   g_Z[i] = 0.0f;
}

__global__ void k_count(const int* __restrict__ dst, int e) {
    int i = blockIdx.x * blockDim.x + threadIdx.x;
    if (i < e) atomicAdd(&g_dinv[dst[i]], 1.0f);
}

__global__ void k_rsqrt(int n) {
    int i = blockIdx.x * blockDim.x + threadIdx.x;
    if (i < n) g_dinv[i] = rsqrtf(g_dinv[i]);
}

// ---------------- register-tiled fp32 GEMM -----------------------------------
// out[i,:] = A[i,:] @ W  (K x C), then either:
//   TANH=false: v = acc * scale[row]; store to out0 AND out1 (agg init = self loop)
//   TANH=true : v = tanhf(acc + bias[col]); store to out0
template <int K, int C, bool TANH>
__global__ void gemm_kernel(const float* __restrict__ A,
                            const float* __restrict__ W,
                            const float* __restrict__ sb,
                            float* __restrict__ out0,
                            float* __restrict__ out1,
                            int n) {
    constexpr int BM  = 128;
    constexpr int TN  = 4;
    constexpr int NCG = C / TN;      // 32 (C=128) or 16 (C=64)
    constexpr int NRG = 256 / NCG;   // 8 or 16
    constexpr int TM  = BM / NRG;    // 16 or 8
    constexpr int KC  = 32;

    __shared__ float Ash[BM * KC];
    __shared__ float Bsh[KC * C];

    int tid = threadIdx.x;
    int m0  = blockIdx.x * BM;
    int tc  = tid % NCG;
    int tr  = tid / NCG;

    float acc[TM][TN];
#pragma unroll
    for (int i = 0; i < TM; i++)
#pragma unroll
        for (int j = 0; j < TN; j++) acc[i][j] = 0.0f;

    for (int kc = 0; kc < K; kc += KC) {
        constexpr int AF4 = BM * KC / 4;
#pragma unroll
        for (int t = tid; t < AF4; t += 256) {
            int r  = t / (KC / 4);
            int c4 = t % (KC / 4);
            float4 v = make_float4(0.f, 0.f, 0.f, 0.f);
            int row = m0 + r;
            if (row < n)
                v = *reinterpret_cast<const float4*>(&A[(size_t)row * K + kc + c4 * 4]);
            *reinterpret_cast<float4*>(&Ash[r * KC + c4 * 4]) = v;
        }
        constexpr int BF4 = KC * C / 4;
#pragma unroll
        for (int t = tid; t < BF4; t += 256) {
            int r  = t / (C / 4);
            int c4 = t % (C / 4);
            *reinterpret_cast<float4*>(&Bsh[r * C + c4 * 4]) =
                *reinterpret_cast<const float4*>(&W[(size_t)(kc + r) * C + c4 * 4]);
        }
        __syncthreads();
#pragma unroll
        for (int k4 = 0; k4 < KC / 4; k4++) {
            float4 b0 = *reinterpret_cast<const float4*>(&Bsh[(k4 * 4 + 0) * C + tc * TN]);
            float4 b1 = *reinterpret_cast<const float4*>(&Bsh[(k4 * 4 + 1) * C + tc * TN]);
            float4 b2 = *reinterpret_cast<const float4*>(&Bsh[(k4 * 4 + 2) * C + tc * TN]);
            float4 b3 = *reinterpret_cast<const float4*>(&Bsh[(k4 * 4 + 3) * C + tc * TN]);
#pragma unroll
            for (int i = 0; i < TM; i++) {
                float4 a = *reinterpret_cast<const float4*>(&Ash[(tr * TM + i) * KC + k4 * 4]);
                acc[i][0] += a.x * b0.x + a.y * b1.x + a.z * b2.x + a.w * b3.x;
                acc[i][1] += a.x * b0.y + a.y * b1.y + a.z * b2.y + a.w * b3.y;
                acc[i][2] += a.x * b0.z + a.y * b1.z + a.z * b2.z + a.w * b3.z;
                acc[i][3] += a.x * b0.w + a.y * b1.w + a.z * b2.w + a.w * b3.w;
            }
        }
        __syncthreads();
    }

#pragma unroll
    for (int i = 0; i < TM; i++) {
        int row = m0 + tr * TM + i;
        if (row >= n) continue;
        size_t base = (size_t)row * C + tc * TN;
        if (TANH) {
            float4 o;
            o.x = tanhf(acc[i][0] + sb[tc * TN + 0]);
            o.y = tanhf(acc[i][1] + sb[tc * TN + 1]);
            o.z = tanhf(acc[i][2] + sb[tc * TN + 2]);
            o.w = tanhf(acc[i][3] + sb[tc * TN + 3]);
            *reinterpret_cast<float4*>(&out0[base]) = o;
        } else {
            float sc = sb[row];
            float4 o = make_float4(acc[i][0] * sc, acc[i][1] * sc,
                                   acc[i][2] * sc, acc[i][3] * sc);
            *reinterpret_cast<float4*>(&out0[base]) = o;
            *reinterpret_cast<float4*>(&out1[base]) = o;
        }
    }
}

// ---------------- edge scatter: warp per edge --------------------------------
template <int VEC> // VEC=4 -> C=128, VEC=2 -> C=64
__global__ void scatter_kernel(const int* __restrict__ src, const int* __restrict__ dst,
                               const float* __restrict__ hs, float* __restrict__ agg, int e) {
    int gid  = blockIdx.x * blockDim.x + threadIdx.x;
    int w    = gid >> 5;
    int lane = gid & 31;
    if (w >= e) return;
    int s = src[w];
    int d = dst[w];
    constexpr int C = 32 * VEC;
    const float* hp = hs + (size_t)s * C + lane * VEC;
    float* ap       = agg + (size_t)d * C + lane * VEC;
    if (VEC == 4) {
        float4 v = *reinterpret_cast<const float4*>(hp);
        atomicAdd(ap + 0, v.x);
        atomicAdd(ap + 1, v.y);
        atomicAdd(ap + 2, v.z);
        atomicAdd(ap + 3, v.w);
    } else {
        float2 v = *reinterpret_cast<const float2*>(hp);
        atomicAdd(ap + 0, v.x);
        atomicAdd(ap + 1, v.y);
    }
}

// ---------------- post-aggregation: scale + bias (+relu) ---------------------
template <int C, bool RELU>
__global__ void post_kernel(const float* __restrict__ agg, const float* __restrict__ bias,
                            float* __restrict__ out, int total) {
    int i = blockIdx.x * blockDim.x + threadIdx.x;
    if (i >= total) return;
    int r = i / C;
    int f = i - r * C;
    float v = agg[i] * g_dinv[r] + bias[f];
    if (RELU) v = fmaxf(v, 0.0f);
    out[i] = v;
}

// ---------------- attention logits s = a1@Wf2+bf2, fused Z accumulation ------
__global__ void k_logits(const float* __restrict__ a1, const float* __restrict__ Wf2,
                         const float* __restrict__ bf2, int n) {
    __shared__ float Wsh[64 * 8];
    __shared__ float bsh[8];
    __shared__ float red[256];
    int tid = threadIdx.x;
    for (int t = tid; t < 512; t += 256) Wsh[t] = Wf2[t];
    if (tid < 8) bsh[tid] = bf2[tid];
    __syncthreads();

    int node = blockIdx.x * 32 + (tid >> 3);
    int d    = tid & 7;
    float e  = 0.0f;
    if (node < n) {
        float acc = bsh[d];
        const float* ar = a1 + (size_t)node * 64;
#pragma unroll 8
        for (int j = 0; j < 64; j++) acc += ar[j] * Wsh[j * 8 + d];
        g_s[(size_t)node * 8 + d] = acc;
        e = expf(acc);
    }
    red[tid] = e;
    __syncthreads();
    for (int off = 128; off >= 8; off >>= 1) {
        if (tid < off) red[tid] += red[tid + off];
        __syncthreads();
    }
    if (tid < 8) atomicAdd(&g_Z[tid], red[tid]);
}

// ---------------- pooled reductions: G = e.T@h2, C = e.T@e -------------------
__global__ void k_accum(int n) {
    __shared__ float h2sh[64 * 64];
    __shared__ float esh[64 * 8];
    int tid = threadIdx.x;
    int c0  = blockIdx.x * 64;
    int nv  = n - c0;
    if (nv > 64) nv = 64;

    for (int t = tid; t < 64 * 64; t += 256) {
        int row = t >> 6;
        if (row < nv) h2sh[t] = g_h2[(size_t)(c0 + row) * 64 + (t & 63)];
    }
    for (int t = tid; t < 512; t += 256) {
        int row = t >> 3;
        if (row < nv) esh[t] = expf(g_s[(size_t)(c0 + row) * 8 + (t & 7)]);
    }
    __syncthreads();

    int p0 = tid, p1 = tid + 256;
    int d0 = p0 >> 6, h0 = p0 & 63;
    int d1 = p1 >> 6, h1 = p1 & 63;
    int cd1 = tid >> 3, cd2 = tid & 7; // valid for tid < 64
    float aG0 = 0.f, aG1 = 0.f, aC = 0.f;
    for (int m = 0; m < nv; m++) {
        float* hrow = &h2sh[m * 64];
        float* erow = &esh[m * 8];
        aG0 += erow[d0] * hrow[h0];
        aG1 += erow[d1] * hrow[h1];
        if (tid < 64) aC += erow[cd1] * erow[cd2];
    }
    atomicAdd(&g_G[p0], aG0);
    atomicAdd(&g_G[p1], aG1);
    if (tid < 64) atomicAdd(&g_C[tid], aC);
}

// ---------------- final: normalize, penalty, dense head, log_softmax ---------
__global__ void k_final(const float* __restrict__ Wl, const float* __restrict__ bl,
                        float* __restrict__ out) {
    __shared__ float ge[512];
    __shared__ float Zs[8];
    __shared__ float tmp[16];
    __shared__ float lg[10];
    int tid = threadIdx.x; // 64 threads
    if (tid < 8) Zs[tid] = g_Z[tid];
    __syncthreads();
    for (int p = tid; p < 512; p += 64) {
        float v = g_G[p] / Zs[p >> 6];
        ge[p]  = v;
        out[p] = v;
    }
    __syncthreads();
    if (tid < 8) {
        float ss = 0.f;
        for (int d2 = 0; d2 < 8; d2++) {
            float c = g_C[tid * 8 + d2] / (Zs[tid] * Zs[d2]) - (tid == d2 ? 1.0f : 0.0f);
            ss += c * c;
        }
        tmp[tid] = sqrtf(ss);
    }
    __syncthreads();
    if (tid == 0) {
        float pen = 0.f;
        for (int d = 0; d < 8; d++) pen += tmp[d];
        out[512] = pen;
    }
    if (tid < 10) {
        float acc = bl[tid];
        for (int p = 0; p < 512; p++) acc += ge[p] * Wl[p * 10 + tid];
        lg[tid] = acc;
    }
    __syncthreads();
    if (tid == 0) {
        float m = lg[0];
        for (int l = 1; l < 10; l++) m = fmaxf(m, lg[l]);
        float s = 0.f;
        for (int l = 0; l < 10; l++) s += expf(lg[l] - m);
        tmp[0] = m + logf(s);
    }
    __syncthreads();
    if (tid < 10) out[513 + tid] = lg[tid] - tmp[0];
}

// ---------------- launch -----------------------------------------------------
extern "C" void kernel_launch(void* const* d_in, const int* in_sizes, int n_in,
                              void* d_out, int out_size) {
    const int*   edges = (const int*)d_in[0];
    const float* X     = (const float*)d_in[1];
    const float* W1    = (const float*)d_in[2];
    const float* b1    = (const float*)d_in[3];
    const float* W2    = (const float*)d_in[4];
    const float* b2    = (const float*)d_in[5];
    const float* Wf1   = (const float*)d_in[6];
    const float* bf1   = (const float*)d_in[7];
    const float* Wf2   = (const float*)d_in[8];
    const float* bf2   = (const float*)d_in[9];
    const float* Wl    = (const float*)d_in[10];
    const float* bl    = (const float*)d_in[11];
    float* out = (float*)d_out;

    int e = in_sizes[0] / 2;
    int n = in_sizes[1] / 128;
    const int* src = edges;
    const int* dst = edges + e;

    float *pA, *pB, *pH2s, *pAgg2, *pH2, *pA1, *pDinv;
    cudaGetSymbolAddress((void**)&pA,    g_bufA);
    cudaGetSymbolAddress((void**)&pB,    g_bufB);
    cudaGetSymbolAddress((void**)&pH2s,  g_h2s);
    cudaGetSymbolAddress((void**)&pAgg2, g_agg2);
    cudaGetSymbolAddress((void**)&pH2,   g_h2);
    cudaGetSymbolAddress((void**)&pA1,   g_a1);
    cudaGetSymbolAddress((void**)&pDinv, g_dinv);

    const int T = 256;
    // degrees -> dinv
    k_init<<<(n + T - 1) / T, T>>>(n);
    k_count<<<(e + T - 1) / T, T>>>(dst, e);
    k_rsqrt<<<(n + T - 1) / T, T>>>(n);

    // layer 1: hs = (X@W1)*dinv, agg init = hs (self loop)
    gemm_kernel<128, 128, false><<<(n + 127) / 128, T>>>(X, W1, pDinv, pA, pB, n);
    scatter_kernel<4><<<(e + 7) / 8, T>>>(src, dst, pA, pB, e);
    post_kernel<128, true><<<((size_t)n * 128 + T - 1) / T, T>>>(pB, b1, pA, n * 128);

    // layer 2
    gemm_kernel<128, 64, false><<<(n + 127) / 128, T>>>(pA, W2, pDinv, pH2s, pAgg2, n);
    scatter_kernel<2><<<(e + 7) / 8, T>>>(src, dst, pH2s, pAgg2, e);
    post_kernel<64, false><<<((size_t)n * 64 + T - 1) / T, T>>>(pAgg2, b2, pH2, n * 64);

    // attention
    gemm_kernel<64, 64, true><<<(n + 127) / 128, T>>>(pH2, Wf1, bf1, pA1, (float*)0, n);
    k_logits<<<(n + 31) / 32, T>>>(pA1, Wf2, bf2, n);
    k_accum<<<(n + 63) / 64, T>>>(n);

    // head
    k_final<<<1, 64>>>(Wl, bl, out);
}

// round 2
// speedup vs baseline: 3.0739x; 3.0739x over previous
#include <cuda_runtime.h>
#include <math.h>

#define MAXN 100000
#define MAXE 3200000

// ---------------- scratch (static device globals; no allocation) -------------
__device__ float g_bufA[(size_t)MAXN * 128]; // hs1 (scaled X@W1)
__device__ float g_bufB[(size_t)MAXN * 128]; // h1 (post conv1)
__device__ float g_h2s [(size_t)MAXN * 64];  // scaled h1@W2
__device__ float g_h2  [(size_t)MAXN * 64];  // h2 (post conv2)
__device__ float g_a1  [(size_t)MAXN * 64];  // tanh(h2@Wf1+bf1)
__device__ float g_s   [(size_t)MAXN * 8];   // exp(attention logits)
__device__ float g_dinv[MAXN];               // deg^{-1/2}
__device__ int   g_cnt [MAXN];               // edge in-degree (no self loop)
__device__ int   g_tmp [MAXN];               // block-inclusive scan values
__device__ int   g_off [MAXN + 1];           // CSR offsets
__device__ int   g_cur [MAXN];               // bucket cursors
__device__ int   g_ecsr[MAXE];               // src ids grouped by dst
__device__ int   g_bsum[128];
__device__ int   g_bpre[128];
__device__ float g_Z[8];                     // sum exp(s) per column
__device__ float g_G[512];                   // unnormalized att.T @ h2  [8,64]
__device__ float g_C[64];                    // unnormalized att.T @ att [8,8]

// ---------------- init / degree / CSR build ----------------------------------
__global__ void k_init(int n) {
    int i = blockIdx.x * blockDim.x + threadIdx.x;
    if (i < n)   g_cnt[i] = 0;
    if (i < 512) g_G[i] = 0.0f;
    if (i < 64)  g_C[i] = 0.0f;
    if (i < 8)   g_Z[i] = 0.0f;
}

__global__ void k_deg(const int* __restrict__ dst, int e) {
    int i = blockIdx.x * blockDim.x + threadIdx.x;
    if (i < e) atomicAdd(&g_cnt[dst[i]], 1);
}

__global__ void k_dinv(int n) {
    int i = blockIdx.x * blockDim.x + threadIdx.x;
    if (i < n) g_dinv[i] = rsqrtf((float)(g_cnt[i] + 1)); // +1 self loop
}

__global__ void k_scan1(int n) {
    __shared__ int sh[1024];
    int i = blockIdx.x * 1024 + threadIdx.x;
    int v = (i < n) ? g_cnt[i] : 0;
    sh[threadIdx.x] = v;
    __syncthreads();
#pragma unroll
    for (int off = 1; off < 1024; off <<= 1) {
        int t = (threadIdx.x >= off) ? sh[threadIdx.x - off] : 0;
        __syncthreads();
        sh[threadIdx.x] += t;
        __syncthreads();
    }
    if (i < n) g_tmp[i] = sh[threadIdx.x];
    if (threadIdx.x == 1023) g_bsum[blockIdx.x] = sh[1023];
}

__global__ void k_scan2(int nb) {
    if (threadIdx.x == 0) {
        int run = 0;
        for (int b = 0; b < nb; b++) { g_bpre[b] = run; run += g_bsum[b]; }
    }
}

__global__ void k_scan3(int n) {
    int i = blockIdx.x * 1024 + threadIdx.x;
    if (i < n) {
        int inc = g_tmp[i] + g_bpre[blockIdx.x];
        g_off[i + 1] = inc;
        g_cur[i]     = inc - g_cnt[i];
    }
    if (i == 0) g_off[0] = 0;
}

__global__ void k_bucket(const int* __restrict__ src, const int* __restrict__ dst, int e) {
    int i = blockIdx.x * blockDim.x + threadIdx.x;
    if (i < e) {
        int d   = dst[i];
        int pos = atomicAdd(&g_cur[d], 1);
        g_ecsr[pos] = src[i];
    }
}

// ---------------- register-tiled fp32 GEMM -----------------------------------
// out[i,:] = A[i,:] @ W.  TANH=false: v = acc * scale[row]; TANH=true: tanh(acc+bias)
template <int K, int C, bool TANH>
__global__ void gemm_kernel(const float* __restrict__ A,
                            const float* __restrict__ W,
                            const float* __restrict__ sb,
                            float* __restrict__ out0,
                            int n) {
    constexpr int BM  = 128;
    constexpr int TN  = 4;
    constexpr int NCG = C / TN;
    constexpr int NRG = 256 / NCG;
    constexpr int TM  = BM / NRG;
    constexpr int KC  = 32;

    __shared__ float Ash[BM * KC];
    __shared__ float Bsh[KC * C];

    int tid = threadIdx.x;
    int m0  = blockIdx.x * BM;
    int tc  = tid % NCG;
    int tr  = tid / NCG;

    float acc[TM][TN];
#pragma unroll
    for (int i = 0; i < TM; i++)
#pragma unroll
        for (int j = 0; j < TN; j++) acc[i][j] = 0.0f;

    for (int kc = 0; kc < K; kc += KC) {
        constexpr int AF4 = BM * KC / 4;
#pragma unroll
        for (int t = tid; t < AF4; t += 256) {
            int r  = t / (KC / 4);
            int c4 = t % (KC / 4);
            float4 v = make_float4(0.f, 0.f, 0.f, 0.f);
            int row = m0 + r;
            if (row < n)
                v = *reinterpret_cast<const float4*>(&A[(size_t)row * K + kc + c4 * 4]);
            *reinterpret_cast<float4*>(&Ash[r * KC + c4 * 4]) = v;
        }
        constexpr int BF4 = KC * C / 4;
#pragma unroll
        for (int t = tid; t < BF4; t += 256) {
            int r  = t / (C / 4);
            int c4 = t % (C / 4);
            *reinterpret_cast<float4*>(&Bsh[r * C + c4 * 4]) =
                *reinterpret_cast<const float4*>(&W[(size_t)(kc + r) * C + c4 * 4]);
        }
        __syncthreads();
#pragma unroll
        for (int k4 = 0; k4 < KC / 4; k4++) {
            float4 b0 = *reinterpret_cast<const float4*>(&Bsh[(k4 * 4 + 0) * C + tc * TN]);
            float4 b1 = *reinterpret_cast<const float4*>(&Bsh[(k4 * 4 + 1) * C + tc * TN]);
            float4 b2 = *reinterpret_cast<const float4*>(&Bsh[(k4 * 4 + 2) * C + tc * TN]);
            float4 b3 = *reinterpret_cast<const float4*>(&Bsh[(k4 * 4 + 3) * C + tc * TN]);
#pragma unroll
            for (int i = 0; i < TM; i++) {
                float4 a = *reinterpret_cast<const float4*>(&Ash[(tr * TM + i) * KC + k4 * 4]);
                acc[i][0] += a.x * b0.x + a.y * b1.x + a.z * b2.x + a.w * b3.x;
                acc[i][1] += a.x * b0.y + a.y * b1.y + a.z * b2.y + a.w * b3.y;
                acc[i][2] += a.x * b0.z + a.y * b1.z + a.z * b2.z + a.w * b3.z;
                acc[i][3] += a.x * b0.w + a.y * b1.w + a.z * b2.w + a.w * b3.w;
            }
        }
        __syncthreads();
    }

#pragma unroll
    for (int i = 0; i < TM; i++) {
        int row = m0 + tr * TM + i;
        if (row >= n) continue;
        size_t base = (size_t)row * C + tc * TN;
        if (TANH) {
            float4 o;
            o.x = tanhf(acc[i][0] + sb[tc * TN + 0]);
            o.y = tanhf(acc[i][1] + sb[tc * TN + 1]);
            o.z = tanhf(acc[i][2] + sb[tc * TN + 2]);
            o.w = tanhf(acc[i][3] + sb[tc * TN + 3]);
            *reinterpret_cast<float4*>(&out0[base]) = o;
        } else {
            float sc = sb[row];
            float4 o = make_float4(acc[i][0] * sc, acc[i][1] * sc,
                                   acc[i][2] * sc, acc[i][3] * sc);
            *reinterpret_cast<float4*>(&out0[base]) = o;
        }
    }
}

// ---------------- CSR gather aggregation (no atomics) -------------------------
// warp per dst node: acc = hs[dst] (self loop) + sum_{s in N(dst)} hs[s]
// out[dst] = acc * dinv[dst] + bias  (+relu)
__global__ void gather128(const float* __restrict__ hs, const float* __restrict__ bias,
                          float* __restrict__ out, int n, int relu) {
    int warp = (blockIdx.x * blockDim.x + threadIdx.x) >> 5;
    int lane = threadIdx.x & 31;
    if (warp >= n) return;
    const int node = warp;
    float4 acc = *reinterpret_cast<const float4*>(&hs[(size_t)node * 128 + lane * 4]);
    int j = g_off[node], jend = g_off[node + 1];
    for (; j + 2 <= jend; j += 2) {
        int s0 = __ldg(&g_ecsr[j]);
        int s1 = __ldg(&g_ecsr[j + 1]);
        float4 v0 = *reinterpret_cast<const float4*>(&hs[(size_t)s0 * 128 + lane * 4]);
        float4 v1 = *reinterpret_cast<const float4*>(&hs[(size_t)s1 * 128 + lane * 4]);
        acc.x += v0.x + v1.x; acc.y += v0.y + v1.y;
        acc.z += v0.z + v1.z; acc.w += v0.w + v1.w;
    }
    if (j < jend) {
        int s0 = __ldg(&g_ecsr[j]);
        float4 v0 = *reinterpret_cast<const float4*>(&hs[(size_t)s0 * 128 + lane * 4]);
        acc.x += v0.x; acc.y += v0.y; acc.z += v0.z; acc.w += v0.w;
    }
    float di = g_dinv[node];
    float4 bb = *reinterpret_cast<const float4*>(&bias[lane * 4]);
    float4 o  = make_float4(acc.x * di + bb.x, acc.y * di + bb.y,
                            acc.z * di + bb.z, acc.w * di + bb.w);
    if (relu) {
        o.x = fmaxf(o.x, 0.f); o.y = fmaxf(o.y, 0.f);
        o.z = fmaxf(o.z, 0.f); o.w = fmaxf(o.w, 0.f);
    }
    *reinterpret_cast<float4*>(&out[(size_t)node * 128 + lane * 4]) = o;
}

__global__ void gather64(const float* __restrict__ hs, const float* __restrict__ bias,
                         float* __restrict__ out, int n) {
    int warp = (blockIdx.x * blockDim.x + threadIdx.x) >> 5;
    int lane = threadIdx.x & 31;
    if (warp >= n) return;
    const int node = warp;
    float2 acc = *reinterpret_cast<const float2*>(&hs[(size_t)node * 64 + lane * 2]);
    int j = g_off[node], jend = g_off[node + 1];
    for (; j + 2 <= jend; j += 2) {
        int s0 = __ldg(&g_ecsr[j]);
        int s1 = __ldg(&g_ecsr[j + 1]);
        float2 v0 = *reinterpret_cast<const float2*>(&hs[(size_t)s0 * 64 + lane * 2]);
        float2 v1 = *reinterpret_cast<const float2*>(&hs[(size_t)s1 * 64 + lane * 2]);
        acc.x += v0.x + v1.x; acc.y += v0.y + v1.y;
    }
    if (j < jend) {
        int s0 = __ldg(&g_ecsr[j]);
        float2 v0 = *reinterpret_cast<const float2*>(&hs[(size_t)s0 * 64 + lane * 2]);
        acc.x += v0.x; acc.y += v0.y;
    }
    float di = g_dinv[node];
    float2 bb = *reinterpret_cast<const float2*>(&bias[lane * 2]);
    float2 o  = make_float2(acc.x * di + bb.x, acc.y * di + bb.y);
    *reinterpret_cast<float2*>(&out[(size_t)node * 64 + lane * 2]) = o;
}

// ---------------- attention logits -> exp(s), fused Z accumulation ------------
__global__ void k_logits(const float* __restrict__ a1, const float* __restrict__ Wf2,
                         const float* __restrict__ bf2, int n) {
    __shared__ float Wsh[64 * 8];
    __shared__ float bsh[8];
    __shared__ float red[256];
    int tid = threadIdx.x;
    for (int t = tid; t < 512; t += 256) Wsh[t] = Wf2[t];
    if (tid < 8) bsh[tid] = bf2[tid];
    __syncthreads();

    int node = blockIdx.x * 32 + (tid >> 3);
    int d    = tid & 7;
    float e  = 0.0f;
    if (node < n) {
        float acc = bsh[d];
        const float* ar = a1 + (size_t)node * 64;
#pragma unroll 8
        for (int j = 0; j < 64; j++) acc += ar[j] * Wsh[j * 8 + d];
        e = expf(acc);
        g_s[(size_t)node * 8 + d] = e;   // store exp(s)
    }
    red[tid] = e;
    __syncthreads();
    for (int off = 128; off >= 8; off >>= 1) {
        if (tid < off) red[tid] += red[tid + off];
        __syncthreads();
    }
    if (tid < 8) atomicAdd(&g_Z[tid], red[tid]);
}

// ---------------- pooled reductions: G = e.T@h2, C = e.T@e --------------------
__global__ void k_accum(int n) {
    __shared__ float h2sh[64 * 64];
    __shared__ float esh[64 * 8];
    int tid = threadIdx.x;
    int c0  = blockIdx.x * 64;
    int nv  = n - c0;
    if (nv > 64) nv = 64;

    for (int t = tid; t < 64 * 64; t += 256) {
        int row = t >> 6;
        if (row < nv) h2sh[t] = g_h2[(size_t)(c0 + row) * 64 + (t & 63)];
    }
    for (int t = tid; t < 512; t += 256) {
        int row = t >> 3;
        if (row < nv) esh[t] = g_s[(size_t)(c0 + row) * 8 + (t & 7)];
    }
    __syncthreads();

    int p0 = tid, p1 = tid + 256;
    int d0 = p0 >> 6, h0 = p0 & 63;
    int d1 = p1 >> 6, h1 = p1 & 63;
    int cd1 = tid >> 3, cd2 = tid & 7;
    float aG0 = 0.f, aG1 = 0.f, aC = 0.f;
    for (int m = 0; m < nv; m++) {
        float* hrow = &h2sh[m * 64];
        float* erow = &esh[m * 8];
        aG0 += erow[d0] * hrow[h0];
        aG1 += erow[d1] * hrow[h1];
        if (tid < 64) aC += erow[cd1] * erow[cd2];
    }
    atomicAdd(&g_G[p0], aG0);
    atomicAdd(&g_G[p1], aG1);
    if (tid < 64) atomicAdd(&g_C[tid], aC);
}

// ---------------- final: normalize, penalty, dense head, log_softmax ----------
__global__ void k_final(const float* __restrict__ Wl, const float* __restrict__ bl,
                        float* __restrict__ out) {
    __shared__ float ge[512];
    __shared__ float Zs[8];
    __shared__ float tmp[16];
    __shared__ float lg[10];
    int tid = threadIdx.x; // 64 threads
    if (tid < 8) Zs[tid] = g_Z[tid];
    __syncthreads();
    for (int p = tid; p < 512; p += 64) {
        float v = g_G[p] / Zs[p >> 6];
        ge[p]  = v;
        out[p] = v;
    }
    __syncthreads();
    if (tid < 8) {
        float ss = 0.f;
        for (int d2 = 0; d2 < 8; d2++) {
            float c = g_C[tid * 8 + d2] / (Zs[tid] * Zs[d2]) - (tid == d2 ? 1.0f : 0.0f);
            ss += c * c;
        }
        tmp[tid] = sqrtf(ss);
    }
    __syncthreads();
    if (tid == 0) {
        float pen = 0.f;
        for (int d = 0; d < 8; d++) pen += tmp[d];
        out[512] = pen;
    }
    if (tid < 10) {
        float acc = bl[tid];
        for (int p = 0; p < 512; p++) acc += ge[p] * Wl[p * 10 + tid];
        lg[tid] = acc;
    }
    __syncthreads();
    if (tid == 0) {
        float m = lg[0];
        for (int l = 1; l < 10; l++) m = fmaxf(m, lg[l]);
        float s = 0.f;
        for (int l = 0; l < 10; l++) s += expf(lg[l] - m);
        tmp[0] = m + logf(s);
    }
    __syncthreads();
    if (tid < 10) out[513 + tid] = lg[tid] - tmp[0];
}

// ---------------- launch -------------------------------------------------------
extern "C" void kernel_launch(void* const* d_in, const int* in_sizes, int n_in,
                              void* d_out, int out_size) {
    const int*   edges = (const int*)d_in[0];
    const float* X     = (const float*)d_in[1];
    const float* W1    = (const float*)d_in[2];
    const float* b1    = (const float*)d_in[3];
    const float* W2    = (const float*)d_in[4];
    const float* b2    = (const float*)d_in[5];
    const float* Wf1   = (const float*)d_in[6];
    const float* bf1   = (const float*)d_in[7];
    const float* Wf2   = (const float*)d_in[8];
    const float* bf2   = (const float*)d_in[9];
    const float* Wl    = (const float*)d_in[10];
    const float* bl    = (const float*)d_in[11];
    float* out = (float*)d_out;

    int e = in_sizes[0] / 2;
    int n = in_sizes[1] / 128;
    const int* src = edges;
    const int* dst = edges + e;

    float *pA, *pB, *pH2s, *pH2, *pA1, *pDinv;
    cudaGetSymbolAddress((void**)&pA,    g_bufA);
    cudaGetSymbolAddress((void**)&pB,    g_bufB);
    cudaGetSymbolAddress((void**)&pH2s,  g_h2s);
    cudaGetSymbolAddress((void**)&pH2,   g_h2);
    cudaGetSymbolAddress((void**)&pA1,   g_a1);
    cudaGetSymbolAddress((void**)&pDinv, g_dinv);

    const int T  = 256;
    const int NB = (n + 1023) / 1024;

    // CSR build + dinv
    k_init  <<<(n + T - 1) / T, T>>>(n);
    k_deg   <<<(e + T - 1) / T, T>>>(dst, e);
    k_dinv  <<<(n + T - 1) / T, T>>>(n);
    k_scan1 <<<NB, 1024>>>(n);
    k_scan2 <<<1, 32>>>(NB);
    k_scan3 <<<NB, 1024>>>(n);
    k_bucket<<<(e + T - 1) / T, T>>>(src, dst, e);

    // layer 1: hs1 = (X@W1)*dinv; h1 = relu(gather(hs1)*dinv + b1)
    gemm_kernel<128, 128, false><<<(n + 127) / 128, T>>>(X, W1, pDinv, pA, n);
    gather128<<<(n + 7) / 8, T>>>(pA, b1, pB, n, 1);

    // layer 2: h2s = (h1@W2)*dinv; h2 = gather(h2s)*dinv + b2
    gemm_kernel<128, 64, false><<<(n + 127) / 128, T>>>(pB, W2, pDinv, pH2s, n);
    gather64<<<(n + 7) / 8, T>>>(pH2s, b2, pH2, n);

    // attention
    gemm_kernel<64, 64, true><<<(n + 127) / 128, T>>>(pH2, Wf1, bf1, pA1, n);
    k_logits<<<(n + 31) / 32, T>>>(pA1, Wf2, bf2, n);
    k_accum <<<(n + 63) / 64, T>>>(n);

    // head
    k_final<<<1, 64>>>(Wl, bl, out);
}